// round 1
// baseline (speedup 1.0000x reference)
#include <cuda_runtime.h>
#include <math.h>

#define NN 50000
#define EE 400000
#define GG 512
#define FF 128
#define KK 4
#define HH 64
#define KH 256   // K*H

// ---------------- device scratch (static, no runtime allocation) ----------------
__device__ float g_z[NN * KH];     // z = x @ W           [N, K, H]
__device__ float g_rst[NN * KH];   // aggregation target  [N, K, H]
__device__ float g_res[NN * KH];   // layer-0 residual GEMM output
__device__ float g_x[NN * KH];     // node features between layers
__device__ float g_el[NN * KK];
__device__ float g_er[NN * KK];
__device__ float g_m[NN * KK];     // segment max per (dst,k)
__device__ float g_s[NN * KK];     // segment expsum per (dst,k)
__device__ float g_e[EE * KK];     // exp(score - max) per edge
__device__ float g_x3[NN * HH];    // layer-2 output (head-mean) [N, 64]
__device__ float g_gs[GG * HH];    // weighted sum readout
__device__ float g_gm[GG * HH];    // max readout

__device__ __forceinline__ void atomicMaxF(float* addr, float v) {
    // monotonic int/uint trick; valid for all finite floats and -inf init
    if (v >= 0.0f) atomicMax((int*)addr, __float_as_int(v));
    else           atomicMin((unsigned int*)addr, __float_as_uint(v));
}

// ---------------- GEMM: C[n x 256] = A[n x din] @ B[din x 256] ----------------
// 64x64 tile, BK=16, 256 threads, 4x4 micro-tile per thread.
__global__ void gemm64(const float* __restrict__ A, const float* __restrict__ B,
                       float* __restrict__ C, int n, int din) {
    __shared__ float As[16][64];
    __shared__ float Bs[16][64];
    const int tid  = threadIdx.x;
    const int row0 = blockIdx.y * 64;
    const int col0 = blockIdx.x * 64;
    const int ar = tid >> 2;         // 0..63
    const int ac = (tid & 3) * 4;    // 0,4,8,12
    const int br = tid >> 4;         // 0..15
    const int bc = (tid & 15) * 4;   // 0..60
    const int ty = tid >> 4;         // 0..15
    const int tx = tid & 15;         // 0..15

    float acc[4][4] = {};
    for (int kt = 0; kt < din; kt += 16) {
        float4 av = make_float4(0.f, 0.f, 0.f, 0.f);
        if (row0 + ar < n)
            av = *(const float4*)&A[(size_t)(row0 + ar) * din + kt + ac];
        As[ac + 0][ar] = av.x; As[ac + 1][ar] = av.y;
        As[ac + 2][ar] = av.z; As[ac + 3][ar] = av.w;
        *(float4*)&Bs[br][bc] = *(const float4*)&B[(size_t)(kt + br) * KH + col0 + bc];
        __syncthreads();
#pragma unroll
        for (int kk = 0; kk < 16; kk++) {
            float a[4], b[4];
#pragma unroll
            for (int i = 0; i < 4; i++) a[i] = As[kk][ty * 4 + i];
#pragma unroll
            for (int j = 0; j < 4; j++) b[j] = Bs[kk][tx * 4 + j];
#pragma unroll
            for (int i = 0; i < 4; i++)
#pragma unroll
                for (int j = 0; j < 4; j++) acc[i][j] += a[i] * b[j];
        }
        __syncthreads();
    }
#pragma unroll
    for (int i = 0; i < 4; i++) {
        int r = row0 + ty * 4 + i;
        if (r < n) {
#pragma unroll
            for (int j = 0; j < 4; j++)
                C[(size_t)r * KH + col0 + tx * 4 + j] = acc[i][j];
        }
    }
}

// ---------------- attention projections el/er: warp per node ----------------
__global__ void attn_scores(const float* __restrict__ z, const float* __restrict__ al,
                            const float* __restrict__ arr) {
    int w    = (blockIdx.x * blockDim.x + threadIdx.x) >> 5;
    int lane = threadIdx.x & 31;
    if (w >= NN) return;
    const float* zr = z + (size_t)w * KH;
#pragma unroll
    for (int k = 0; k < 4; k++) {
        float z0 = zr[k * 64 + lane], z1 = zr[k * 64 + lane + 32];
        float vl = z0 * al[k * 64 + lane]  + z1 * al[k * 64 + lane + 32];
        float vr = z0 * arr[k * 64 + lane] + z1 * arr[k * 64 + lane + 32];
#pragma unroll
        for (int off = 16; off; off >>= 1) {
            vl += __shfl_down_sync(0xffffffffu, vl, off);
            vr += __shfl_down_sync(0xffffffffu, vr, off);
        }
        if (lane == 0) { g_el[w * 4 + k] = vl; g_er[w * 4 + k] = vr; }
    }
}

// ---------------- per-layer scratch init ----------------
__global__ void init_layer() {
    int i = blockIdx.x * blockDim.x + threadIdx.x;
    if (i < NN * KH) g_rst[i] = 0.0f;
    if (i < NN * KK) { g_m[i] = __int_as_float(0xff800000); g_s[i] = 0.0f; }
}

__device__ __forceinline__ float leaky02(float v) { return v > 0.0f ? v : 0.2f * v; }

// ---------------- edge pass 1: segment max of leaky scores ----------------
__global__ void edge_max(const int* __restrict__ src, const int* __restrict__ dst) {
    int e = blockIdx.x * blockDim.x + threadIdx.x;
    if (e >= EE) return;
    int sn = src[e], dn = dst[e];
    float4 l = *(const float4*)&g_el[sn * 4];
    float4 r = *(const float4*)&g_er[dn * 4];
    atomicMaxF(&g_m[dn * 4 + 0], leaky02(l.x + r.x));
    atomicMaxF(&g_m[dn * 4 + 1], leaky02(l.y + r.y));
    atomicMaxF(&g_m[dn * 4 + 2], leaky02(l.z + r.z));
    atomicMaxF(&g_m[dn * 4 + 3], leaky02(l.w + r.w));
}

// ---------------- edge pass 2: exp + segment sum ----------------
__global__ void edge_sum(const int* __restrict__ src, const int* __restrict__ dst) {
    int e = blockIdx.x * blockDim.x + threadIdx.x;
    if (e >= EE) return;
    int sn = src[e], dn = dst[e];
    float4 l = *(const float4*)&g_el[sn * 4];
    float4 r = *(const float4*)&g_er[dn * 4];
    float4 m = *(const float4*)&g_m[dn * 4];
    float4 ee;
    ee.x = expf(leaky02(l.x + r.x) - m.x);
    ee.y = expf(leaky02(l.y + r.y) - m.y);
    ee.z = expf(leaky02(l.z + r.z) - m.z);
    ee.w = expf(leaky02(l.w + r.w) - m.w);
    *(float4*)&g_e[e * 4] = ee;
    atomicAdd(&g_s[dn * 4 + 0], ee.x);
    atomicAdd(&g_s[dn * 4 + 1], ee.y);
    atomicAdd(&g_s[dn * 4 + 2], ee.z);
    atomicAdd(&g_s[dn * 4 + 3], ee.w);
}

// ---------------- edge pass 3: a * z[src] scatter into rst[dst]; warp per edge ----------------
__global__ void edge_aggr(const int* __restrict__ src, const int* __restrict__ dst) {
    int w    = (blockIdx.x * blockDim.x + threadIdx.x) >> 5;
    int lane = threadIdx.x & 31;
    if (w >= EE) return;
    int sn = src[w], dn = dst[w];
    float4 ee = *(const float4*)&g_e[w * 4];
    float4 sv = *(const float4*)&g_s[dn * 4];
    float a[4] = { ee.x / sv.x, ee.y / sv.y, ee.z / sv.z, ee.w / sv.w };
    const float* zr = g_z + (size_t)sn * KH;
    float* rr = g_rst + (size_t)dn * KH;
#pragma unroll
    for (int k = 0; k < 4; k++) {
        atomicAdd(&rr[k * 64 + lane],      a[k] * zr[k * 64 + lane]);
        atomicAdd(&rr[k * 64 + lane + 32], a[k] * zr[k * 64 + lane + 32]);
    }
}

// ---------------- combine: relu(rst + res + b), flatten ----------------
__global__ void combine_flat(const float* __restrict__ res, const float* __restrict__ b,
                             float* __restrict__ xout) {
    int i = blockIdx.x * blockDim.x + threadIdx.x;
    if (i >= NN * KH) return;
    float v = g_rst[i] + res[i] + b[i & 255];
    xout[i] = v > 0.0f ? v : 0.0f;
}

// ---------------- combine: relu then mean over heads -> [N, 64] ----------------
__global__ void combine_mean(const float* __restrict__ res, const float* __restrict__ b) {
    int i = blockIdx.x * blockDim.x + threadIdx.x;
    if (i >= NN * HH) return;
    int n = i >> 6, hh = i & 63;
    float acc = 0.0f;
#pragma unroll
    for (int k = 0; k < 4; k++) {
        int j = n * KH + k * 64 + hh;
        float v = g_rst[j] + res[j] + b[k * 64 + hh];
        acc += (v > 0.0f ? v : 0.0f);
    }
    g_x3[i] = acc * 0.25f;
}

// ---------------- readout init ----------------
__global__ void init_readout() {
    int i = blockIdx.x * blockDim.x + threadIdx.x;
    if (i < GG * HH) { g_gs[i] = 0.0f; g_gm[i] = __int_as_float(0xff800000); }
}

// ---------------- WeightedSumAndMax readout: warp per node ----------------
__global__ void readout(const int* __restrict__ gid, const float* __restrict__ Wg,
                        const float* __restrict__ bg) {
    int w    = (blockIdx.x * blockDim.x + threadIdx.x) >> 5;
    int lane = threadIdx.x & 31;
    if (w >= NN) return;
    int g = gid[w];
    const float* xr = g_x3 + (size_t)w * 64;
    float x0 = xr[lane], x1 = xr[lane + 32];
    float p = x0 * Wg[lane] + x1 * Wg[lane + 32];
#pragma unroll
    for (int off = 16; off; off >>= 1) p += __shfl_down_sync(0xffffffffu, p, off);
    p = __shfl_sync(0xffffffffu, p, 0);
    float wgt = 1.0f / (1.0f + expf(-(p + bg[0])));
    atomicAdd(&g_gs[g * 64 + lane],      wgt * x0);
    atomicAdd(&g_gs[g * 64 + lane + 32], wgt * x1);
    atomicMaxF(&g_gm[g * 64 + lane],      x0);
    atomicMaxF(&g_gm[g * 64 + lane + 32], x1);
}

// ---------------- MLP head: one block per graph ----------------
__global__ void mlp_head(const float* __restrict__ Wm1, const float* __restrict__ bm1,
                         const float* __restrict__ bn_g, const float* __restrict__ bn_b,
                         const float* __restrict__ bn_m, const float* __restrict__ bn_v,
                         const float* __restrict__ Wm2, const float* __restrict__ bm2,
                         float* __restrict__ out) {
    int g = blockIdx.x, j = threadIdx.x;   // 64 threads
    __shared__ float gf[128];
    gf[j]      = g_gs[g * 64 + j];
    gf[j + 64] = g_gm[g * 64 + j];
    __syncthreads();
    float acc = bm1[j];
#pragma unroll 8
    for (int i = 0; i < 128; i++) acc += gf[i] * Wm1[i * 64 + j];
    float y = acc > 0.0f ? acc : 0.0f;
    y = (y - bn_m[j]) * rsqrtf(bn_v[j] + 1e-5f) * bn_g[j] + bn_b[j];
    __shared__ float red[64];
    red[j] = y * Wm2[j];
    __syncthreads();
    if (j == 0) {
        float t = 0.0f;
#pragma unroll
        for (int i = 0; i < 64; i++) t += red[i];
        out[g] = 1.0f / (1.0f + expf(-(t + bm2[0])));
    }
}

// ---------------- host launcher ----------------
extern "C" void kernel_launch(void* const* d_in, const int* in_sizes, int n_in,
                              void* d_out, int out_size) {
    (void)in_sizes; (void)n_in; (void)out_size;
    const float* h     = (const float*)d_in[0];
    const int*   src   = (const int*)d_in[1];
    const int*   dst   = (const int*)d_in[2];
    const int*   gid   = (const int*)d_in[3];
    const float* W0    = (const float*)d_in[4];
    const float* al0   = (const float*)d_in[5];
    const float* ar0   = (const float*)d_in[6];
    const float* b0    = (const float*)d_in[7];
    const float* resW0 = (const float*)d_in[8];
    const float* W1    = (const float*)d_in[9];
    const float* al1   = (const float*)d_in[10];
    const float* ar1   = (const float*)d_in[11];
    const float* b1    = (const float*)d_in[12];
    const float* W2    = (const float*)d_in[13];
    const float* al2   = (const float*)d_in[14];
    const float* ar2   = (const float*)d_in[15];
    const float* b2    = (const float*)d_in[16];
    const float* Wg    = (const float*)d_in[17];
    const float* bg    = (const float*)d_in[18];
    const float* Wm1   = (const float*)d_in[19];
    const float* bm1   = (const float*)d_in[20];
    const float* bng   = (const float*)d_in[21];
    const float* bnb   = (const float*)d_in[22];
    const float* bnm   = (const float*)d_in[23];
    const float* bnv   = (const float*)d_in[24];
    const float* Wm2   = (const float*)d_in[25];
    const float* bm2   = (const float*)d_in[26];

    float *p_z, *p_res, *p_x;
    cudaGetSymbolAddress((void**)&p_z,   g_z);
    cudaGetSymbolAddress((void**)&p_res, g_res);
    cudaGetSymbolAddress((void**)&p_x,   g_x);

    dim3 gemmGrid(4, (NN + 63) / 64);
    const int initB  = (NN * KH + 255) / 256;
    const int edgeB  = (EE + 255) / 256;
    const int eWarpB = (EE + 7) / 8;      // warp per edge, 8 warps/block
    const int nWarpB = (NN + 7) / 8;      // warp per node

    // ---- Layer 0 (flatten, learned residual) ----
    gemm64<<<gemmGrid, 256>>>(h, W0, p_z, NN, FF);
    gemm64<<<gemmGrid, 256>>>(h, resW0, p_res, NN, FF);
    attn_scores<<<nWarpB, 256>>>(p_z, al0, ar0);
    init_layer<<<initB, 256>>>();
    edge_max<<<edgeB, 256>>>(src, dst);
    edge_sum<<<edgeB, 256>>>(src, dst);
    edge_aggr<<<eWarpB, 256>>>(src, dst);
    combine_flat<<<initB, 256>>>(p_res, b0, p_x);

    // ---- Layer 1 (flatten, identity residual) ----
    gemm64<<<gemmGrid, 256>>>(p_x, W1, p_z, NN, KH);
    attn_scores<<<nWarpB, 256>>>(p_z, al1, ar1);
    init_layer<<<initB, 256>>>();
    edge_max<<<edgeB, 256>>>(src, dst);
    edge_sum<<<edgeB, 256>>>(src, dst);
    edge_aggr<<<eWarpB, 256>>>(src, dst);
    combine_flat<<<initB, 256>>>(p_x, b1, p_x);   // in-place: same-index elementwise

    // ---- Layer 2 (mean over heads, identity residual) ----
    gemm64<<<gemmGrid, 256>>>(p_x, W2, p_z, NN, KH);
    attn_scores<<<nWarpB, 256>>>(p_z, al2, ar2);
    init_layer<<<initB, 256>>>();
    edge_max<<<edgeB, 256>>>(src, dst);
    edge_sum<<<edgeB, 256>>>(src, dst);
    edge_aggr<<<eWarpB, 256>>>(src, dst);
    combine_mean<<<(NN * HH + 255) / 256, 256>>>(p_x, b2);

    // ---- Readout + MLP ----
    init_readout<<<(GG * HH + 255) / 256, 256>>>();
    readout<<<nWarpB, 256>>>(gid, Wg, bg);
    mlp_head<<<GG, 64>>>(Wm1, bm1, bng, bnb, bnm, bnv, Wm2, bm2, (float*)d_out);
}

// round 2
// speedup vs baseline: 1.6874x; 1.6874x over previous
#include <cuda_runtime.h>
#include <math.h>

#define NN 50000
#define EE 400000
#define GG 512
#define FF 128
#define KK 4
#define HH 64
#define KH 256   // K*H
#define NEG_INF __int_as_float(0xff800000)

// ---------------- device scratch (static, no runtime allocation) ----------------
__device__ float g_z[NN * KH];     // z = x @ W           [N, K, H]
__device__ float g_res[NN * KH];   // layer-0 residual GEMM output
__device__ float g_x[NN * KH];     // node features between layers
__device__ float g_el[NN * KK];
__device__ float g_er[NN * KK];
__device__ float g_x3[NN * HH];    // layer-2 output (head-mean) [N, 64]
__device__ float g_gs[GG * HH];    // weighted sum readout
__device__ float g_gm[GG * HH];    // max readout
// CSR (incoming edges grouped by dst)
__device__ int g_rowptr[NN + 1];
__device__ int g_cnt[NN];
__device__ int g_fill[NN];
__device__ int g_csrc[EE];

__device__ __forceinline__ void atomicMaxF(float* addr, float v) {
    if (v >= 0.0f) atomicMax((int*)addr, __float_as_int(v));
    else           atomicMin((unsigned int*)addr, __float_as_uint(v));
}
__device__ __forceinline__ float leaky02(float v) { return v > 0.0f ? v : 0.2f * v; }

// ================= CSR build =================
__global__ void csr_zero() {
    int i = blockIdx.x * blockDim.x + threadIdx.x;
    if (i < NN) { g_cnt[i] = 0; g_fill[i] = 0; }
}
__global__ void csr_hist(const int* __restrict__ dst) {
    int e = blockIdx.x * blockDim.x + threadIdx.x;
    if (e < EE) atomicAdd(&g_cnt[dst[e]], 1);
}
// single-block (1024 thread) exclusive scan of g_cnt -> g_rowptr
__global__ void csr_scan() {
    __shared__ int smW[32];
    __shared__ int sOff;
    int tid = threadIdx.x, lane = tid & 31, wid = tid >> 5;
    if (tid == 0) sOff = 0;
    __syncthreads();
    for (int base = 0; base < NN; base += 1024) {
        int i = base + tid;
        int v = (i < NN) ? g_cnt[i] : 0;
        int inc = v;
#pragma unroll
        for (int o = 1; o < 32; o <<= 1) {
            int t = __shfl_up_sync(0xffffffffu, inc, o);
            if (lane >= o) inc += t;
        }
        if (lane == 31) smW[wid] = inc;
        __syncthreads();
        if (wid == 0) {
            int t = smW[lane];
#pragma unroll
            for (int o = 1; o < 32; o <<= 1) {
                int u = __shfl_up_sync(0xffffffffu, t, o);
                if (lane >= o) t += u;
            }
            smW[lane] = t;
        }
        __syncthreads();
        int warpOff = wid ? smW[wid - 1] : 0;
        if (i < NN) g_rowptr[i] = sOff + warpOff + inc - v;
        int blockTot = smW[31];
        __syncthreads();
        if (tid == 0) sOff += blockTot;
        __syncthreads();
    }
    if (tid == 0) g_rowptr[NN] = sOff;
}
__global__ void csr_fill_k(const int* __restrict__ src, const int* __restrict__ dst) {
    int e = blockIdx.x * blockDim.x + threadIdx.x;
    if (e >= EE) return;
    int d = dst[e];
    int pos = g_rowptr[d] + atomicAdd(&g_fill[d], 1);
    g_csrc[pos] = src[e];
}

// ================= GEMM: C[n x 256] = A[n x din] @ B[din x 256] =================
// 128x64 tile, BK=16, 256 threads, 8x4 micro-tile
__global__ void gemm128(const float* __restrict__ A, const float* __restrict__ B,
                        float* __restrict__ C, int n, int din) {
    __shared__ float As[16][128];
    __shared__ float Bs[16][64];
    const int tid  = threadIdx.x;
    const int row0 = blockIdx.y * 128;
    const int col0 = blockIdx.x * 64;
    const int lar = tid >> 1;            // 0..127
    const int lac = (tid & 1) * 8;       // 0 or 8
    const int lbr = tid >> 4;            // 0..15
    const int lbc = (tid & 15) * 4;      // 0..60
    const int ty  = tid >> 4;            // 0..15
    const int tx  = tid & 15;            // 0..15

    float acc[8][4] = {};
    for (int kt = 0; kt < din; kt += 16) {
#pragma unroll
        for (int q = 0; q < 2; q++) {
            float4 av = make_float4(0.f, 0.f, 0.f, 0.f);
            int gr = row0 + lar;
            if (gr < n) av = *(const float4*)&A[(size_t)gr * din + kt + lac + q * 4];
            int cc = lac + q * 4;
            As[cc + 0][lar] = av.x; As[cc + 1][lar] = av.y;
            As[cc + 2][lar] = av.z; As[cc + 3][lar] = av.w;
        }
        *(float4*)&Bs[lbr][lbc] = *(const float4*)&B[(size_t)(kt + lbr) * KH + col0 + lbc];
        __syncthreads();
#pragma unroll
        for (int kk = 0; kk < 16; kk++) {
            float a[8], b[4];
#pragma unroll
            for (int i = 0; i < 8; i++) a[i] = As[kk][ty * 8 + i];
#pragma unroll
            for (int j = 0; j < 4; j++) b[j] = Bs[kk][tx * 4 + j];
#pragma unroll
            for (int i = 0; i < 8; i++)
#pragma unroll
                for (int j = 0; j < 4; j++) acc[i][j] += a[i] * b[j];
        }
        __syncthreads();
    }
#pragma unroll
    for (int i = 0; i < 8; i++) {
        int r = row0 + ty * 8 + i;
        if (r < n)
            *(float4*)&C[(size_t)r * KH + col0 + tx * 4] =
                make_float4(acc[i][0], acc[i][1], acc[i][2], acc[i][3]);
    }
}

// ================= attention projections el/er: warp per node =================
__global__ void attn_scores(const float* __restrict__ z, const float* __restrict__ al,
                            const float* __restrict__ arr) {
    int w    = (blockIdx.x * blockDim.x + threadIdx.x) >> 5;
    int lane = threadIdx.x & 31;
    if (w >= NN) return;
    const float* zr = z + (size_t)w * KH;
#pragma unroll
    for (int k = 0; k < 4; k++) {
        float z0 = zr[k * 64 + lane], z1 = zr[k * 64 + lane + 32];
        float vl = z0 * al[k * 64 + lane]  + z1 * al[k * 64 + lane + 32];
        float vr = z0 * arr[k * 64 + lane] + z1 * arr[k * 64 + lane + 32];
#pragma unroll
        for (int off = 16; off; off >>= 1) {
            vl += __shfl_down_sync(0xffffffffu, vl, off);
            vr += __shfl_down_sync(0xffffffffu, vr, off);
        }
        if (lane == 0) { g_el[w * 4 + k] = vl; g_er[w * 4 + k] = vr; }
    }
}

// ================= fused GAT attention + aggregation + combine =================
// warp per dst node; CSR gather; no atomics.
// mode 0: flatten -> xout[N,256] = relu(agg + res + b)
// mode 1: mean over heads -> g_x3[N,64]
__global__ void gat_fused(const float* __restrict__ z, const float* __restrict__ res,
                          const float* __restrict__ bias, float* __restrict__ xout,
                          int mode) {
    __shared__ float sm[8][256];
    const int wIB  = threadIdx.x >> 5;
    const int n    = (blockIdx.x * blockDim.x + threadIdx.x) >> 5;
    const int lane = threadIdx.x & 31;
    if (n >= NN) return;
    const int r0 = g_rowptr[n];
    const int nE = g_rowptr[n + 1] - r0;
    const float4 erv = *(const float4*)&g_er[n * 4];
    const int myK = lane >> 3;

    // ---- pass 1: per-head max over incoming edges ----
    float m0 = NEG_INF, m1 = NEG_INF, m2 = NEG_INF, m3 = NEG_INF;
    for (int b = 0; b < nE; b += 32) {
        int idx = b + lane;
        if (idx < nE) {
            int s = g_csrc[r0 + idx];
            float4 l = *(const float4*)&g_el[s * 4];
            m0 = fmaxf(m0, leaky02(l.x + erv.x));
            m1 = fmaxf(m1, leaky02(l.y + erv.y));
            m2 = fmaxf(m2, leaky02(l.z + erv.z));
            m3 = fmaxf(m3, leaky02(l.w + erv.w));
        }
    }
#pragma unroll
    for (int off = 16; off; off >>= 1) {
        m0 = fmaxf(m0, __shfl_xor_sync(0xffffffffu, m0, off));
        m1 = fmaxf(m1, __shfl_xor_sync(0xffffffffu, m1, off));
        m2 = fmaxf(m2, __shfl_xor_sync(0xffffffffu, m2, off));
        m3 = fmaxf(m3, __shfl_xor_sync(0xffffffffu, m3, off));
    }

    // ---- pass 2: unnormalized softmax-weighted aggregation ----
    float acc[8] = {};
    float sl0 = 0.f, sl1 = 0.f, sl2 = 0.f, sl3 = 0.f;
    for (int b = 0; b < nE; b += 32) {
        int idx = b + lane;
        int cnt = min(32, nE - b);
        float p0 = 0.f, p1 = 0.f, p2 = 0.f, p3 = 0.f;
        int sN = 0;
        if (idx < nE) {
            sN = g_csrc[r0 + idx];
            float4 l = *(const float4*)&g_el[sN * 4];
            p0 = __expf(leaky02(l.x + erv.x) - m0);
            p1 = __expf(leaky02(l.y + erv.y) - m1);
            p2 = __expf(leaky02(l.z + erv.z) - m2);
            p3 = __expf(leaky02(l.w + erv.w) - m3);
            sl0 += p0; sl1 += p1; sl2 += p2; sl3 += p3;
        }
        for (int i = 0; i < cnt; i++) {
            int ss   = __shfl_sync(0xffffffffu, sN, i);
            float q0 = __shfl_sync(0xffffffffu, p0, i);
            float q1 = __shfl_sync(0xffffffffu, p1, i);
            float q2 = __shfl_sync(0xffffffffu, p2, i);
            float q3 = __shfl_sync(0xffffffffu, p3, i);
            float pa = (myK == 0) ? q0 : (myK == 1) ? q1 : (myK == 2) ? q2 : q3;
            const float4* zr = (const float4*)(z + (size_t)ss * KH + lane * 8);
            float4 za = zr[0], zb = zr[1];
            acc[0] += pa * za.x; acc[1] += pa * za.y;
            acc[2] += pa * za.z; acc[3] += pa * za.w;
            acc[4] += pa * zb.x; acc[5] += pa * zb.y;
            acc[6] += pa * zb.z; acc[7] += pa * zb.w;
        }
    }
#pragma unroll
    for (int off = 16; off; off >>= 1) {
        sl0 += __shfl_xor_sync(0xffffffffu, sl0, off);
        sl1 += __shfl_xor_sync(0xffffffffu, sl1, off);
        sl2 += __shfl_xor_sync(0xffffffffu, sl2, off);
        sl3 += __shfl_xor_sync(0xffffffffu, sl3, off);
    }
    float sk = (myK == 0) ? sl0 : (myK == 1) ? sl1 : (myK == 2) ? sl2 : sl3;
    float inv = (nE > 0) ? (1.0f / sk) : 0.0f;

    // ---- combine: relu(agg + res + b) ----
    const int base = n * KH + lane * 8;
    float v[8];
    const float4* rp = (const float4*)(res + base);
    const float4* bp = (const float4*)(bias + lane * 8);
    float4 r4a = rp[0], r4b = rp[1], b4a = bp[0], b4b = bp[1];
    v[0] = acc[0] * inv + r4a.x + b4a.x; v[1] = acc[1] * inv + r4a.y + b4a.y;
    v[2] = acc[2] * inv + r4a.z + b4a.z; v[3] = acc[3] * inv + r4a.w + b4a.w;
    v[4] = acc[4] * inv + r4b.x + b4b.x; v[5] = acc[5] * inv + r4b.y + b4b.y;
    v[6] = acc[6] * inv + r4b.z + b4b.z; v[7] = acc[7] * inv + r4b.w + b4b.w;
#pragma unroll
    for (int j = 0; j < 8; j++) v[j] = v[j] > 0.f ? v[j] : 0.f;

    if (mode == 0) {
        float4* op = (float4*)(xout + base);
        op[0] = make_float4(v[0], v[1], v[2], v[3]);
        op[1] = make_float4(v[4], v[5], v[6], v[7]);
    } else {
#pragma unroll
        for (int j = 0; j < 8; j++) sm[wIB][lane * 8 + j] = v[j];
        __syncwarp();
        float h0 = (sm[wIB][lane]      + sm[wIB][64 + lane] +
                    sm[wIB][128 + lane] + sm[wIB][192 + lane]) * 0.25f;
        float h1 = (sm[wIB][32 + lane]  + sm[wIB][96 + lane] +
                    sm[wIB][160 + lane] + sm[wIB][224 + lane]) * 0.25f;
        g_x3[n * 64 + lane]      = h0;
        g_x3[n * 64 + lane + 32] = h1;
    }
}

// ================= readout + MLP =================
__global__ void init_readout() {
    int i = blockIdx.x * blockDim.x + threadIdx.x;
    if (i < GG * HH) { g_gs[i] = 0.0f; g_gm[i] = NEG_INF; }
}
__global__ void readout(const int* __restrict__ gid, const float* __restrict__ Wg,
                        const float* __restrict__ bg) {
    int w    = (blockIdx.x * blockDim.x + threadIdx.x) >> 5;
    int lane = threadIdx.x & 31;
    if (w >= NN) return;
    int g = gid[w];
    const float* xr = g_x3 + (size_t)w * 64;
    float x0 = xr[lane], x1 = xr[lane + 32];
    float p = x0 * Wg[lane] + x1 * Wg[lane + 32];
#pragma unroll
    for (int off = 16; off; off >>= 1) p += __shfl_down_sync(0xffffffffu, p, off);
    p = __shfl_sync(0xffffffffu, p, 0);
    float wgt = 1.0f / (1.0f + expf(-(p + bg[0])));
    atomicAdd(&g_gs[g * 64 + lane],      wgt * x0);
    atomicAdd(&g_gs[g * 64 + lane + 32], wgt * x1);
    atomicMaxF(&g_gm[g * 64 + lane],      x0);
    atomicMaxF(&g_gm[g * 64 + lane + 32], x1);
}
__global__ void mlp_head(const float* __restrict__ Wm1, const float* __restrict__ bm1,
                         const float* __restrict__ bn_g, const float* __restrict__ bn_b,
                         const float* __restrict__ bn_m, const float* __restrict__ bn_v,
                         const float* __restrict__ Wm2, const float* __restrict__ bm2,
                         float* __restrict__ out) {
    int g = blockIdx.x, j = threadIdx.x;   // 64 threads
    __shared__ float gf[128];
    gf[j]      = g_gs[g * 64 + j];
    gf[j + 64] = g_gm[g * 64 + j];
    __syncthreads();
    float acc = bm1[j];
#pragma unroll 8
    for (int i = 0; i < 128; i++) acc += gf[i] * Wm1[i * 64 + j];
    float y = acc > 0.0f ? acc : 0.0f;
    y = (y - bn_m[j]) * rsqrtf(bn_v[j] + 1e-5f) * bn_g[j] + bn_b[j];
    __shared__ float red[64];
    red[j] = y * Wm2[j];
    __syncthreads();
    if (j == 0) {
        float t = 0.0f;
#pragma unroll
        for (int i = 0; i < 64; i++) t += red[i];
        out[g] = 1.0f / (1.0f + expf(-(t + bm2[0])));
    }
}

// ================= host launcher =================
extern "C" void kernel_launch(void* const* d_in, const int* in_sizes, int n_in,
                              void* d_out, int out_size) {
    (void)in_sizes; (void)n_in; (void)out_size;
    const float* h     = (const float*)d_in[0];
    const int*   src   = (const int*)d_in[1];
    const int*   dst   = (const int*)d_in[2];
    const int*   gid   = (const int*)d_in[3];
    const float* W0    = (const float*)d_in[4];
    const float* al0   = (const float*)d_in[5];
    const float* ar0   = (const float*)d_in[6];
    const float* b0    = (const float*)d_in[7];
    const float* resW0 = (const float*)d_in[8];
    const float* W1    = (const float*)d_in[9];
    const float* al1   = (const float*)d_in[10];
    const float* ar1   = (const float*)d_in[11];
    const float* b1    = (const float*)d_in[12];
    const float* W2    = (const float*)d_in[13];
    const float* al2   = (const float*)d_in[14];
    const float* ar2   = (const float*)d_in[15];
    const float* b2    = (const float*)d_in[16];
    const float* Wg    = (const float*)d_in[17];
    const float* bg    = (const float*)d_in[18];
    const float* Wm1   = (const float*)d_in[19];
    const float* bm1   = (const float*)d_in[20];
    const float* bng   = (const float*)d_in[21];
    const float* bnb   = (const float*)d_in[22];
    const float* bnm   = (const float*)d_in[23];
    const float* bnv   = (const float*)d_in[24];
    const float* Wm2   = (const float*)d_in[25];
    const float* bm2   = (const float*)d_in[26];

    float *p_z, *p_res, *p_x;
    cudaGetSymbolAddress((void**)&p_z,   g_z);
    cudaGetSymbolAddress((void**)&p_res, g_res);
    cudaGetSymbolAddress((void**)&p_x,   g_x);

    dim3 gemmGrid(KH / 64, (NN + 127) / 128);
    const int edgeB  = (EE + 255) / 256;
    const int nWarpB = (NN + 7) / 8;      // warp per node, 8 warps/block

    // ---- CSR build (dst-grouped incoming edges) ----
    csr_zero<<<(NN + 255) / 256, 256>>>();
    csr_hist<<<edgeB, 256>>>(dst);
    csr_scan<<<1, 1024>>>();
    csr_fill_k<<<edgeB, 256>>>(src, dst);

    // ---- Layer 0 (flatten, learned residual) ----
    gemm128<<<gemmGrid, 256>>>(h, W0, p_z, NN, FF);
    gemm128<<<gemmGrid, 256>>>(h, resW0, p_res, NN, FF);
    attn_scores<<<nWarpB, 256>>>(p_z, al0, ar0);
    gat_fused<<<nWarpB, 256>>>(p_z, p_res, b0, p_x, 0);

    // ---- Layer 1 (flatten, identity residual) ----
    gemm128<<<gemmGrid, 256>>>(p_x, W1, p_z, NN, KH);
    attn_scores<<<nWarpB, 256>>>(p_z, al1, ar1);
    gat_fused<<<nWarpB, 256>>>(p_z, p_x, b1, p_x, 0);

    // ---- Layer 2 (mean over heads, identity residual) ----
    gemm128<<<gemmGrid, 256>>>(p_x, W2, p_z, NN, KH);
    attn_scores<<<nWarpB, 256>>>(p_z, al2, ar2);
    gat_fused<<<nWarpB, 256>>>(p_z, p_x, b2, nullptr, 1);

    // ---- Readout + MLP ----
    init_readout<<<(GG * HH + 255) / 256, 256>>>();
    readout<<<nWarpB, 256>>>(gid, Wg, bg);
    mlp_head<<<GG, 64>>>(Wm1, bm1, bng, bnb, bnm, bnv, Wm2, bm2, (float*)d_out);
}

// round 4
// speedup vs baseline: 1.9595x; 1.1612x over previous
#include <cuda_runtime.h>
#include <math.h>
#include <stdint.h>

#define NN 50000
#define EE 400000
#define GG 512
#define FF 128
#define KK 4
#define HH 64
#define KH 256   // K*H
#define NEG_INF __int_as_float(0xff800000)

// ---------------- device scratch (static, no runtime allocation) ----------------
__device__ float g_z[NN * KH];     // z = x @ W           [N, K, H]
__device__ float g_res[NN * KH];   // layer-0 residual GEMM output
__device__ float g_x[NN * KH];     // node features between layers
__device__ float g_el[NN * KK];
__device__ float g_er[NN * KK];
__device__ float g_x3[NN * HH];    // layer-2 output (head-mean) [N, 64]
__device__ float g_gs[GG * HH];    // weighted sum readout
__device__ float g_gm[GG * HH];    // max readout
// CSR (incoming edges grouped by dst)
__device__ int g_rowptr[NN + 1];
__device__ int g_cnt[NN];
__device__ int g_fill[NN];
__device__ int g_csrc[EE];

__device__ __forceinline__ void atomicMaxF(float* addr, float v) {
    if (v >= 0.0f) atomicMax((int*)addr, __float_as_int(v));
    else           atomicMin((unsigned int*)addr, __float_as_uint(v));
}
__device__ __forceinline__ float leaky02(float v) { return v > 0.0f ? v : 0.2f * v; }
__device__ __forceinline__ uint32_t f2tf32(float v) {
    uint32_t r;
    asm("cvt.rna.tf32.f32 %0, %1;" : "=r"(r) : "f"(v));
    return r;
}

// ================= CSR build =================
__global__ void csr_zero() {
    int i = blockIdx.x * blockDim.x + threadIdx.x;
    if (i < NN) { g_cnt[i] = 0; g_fill[i] = 0; }
}
__global__ void csr_hist(const int* __restrict__ dst) {
    int e = blockIdx.x * blockDim.x + threadIdx.x;
    if (e < EE) atomicAdd(&g_cnt[dst[e]], 1);
}
__global__ void csr_scan() {
    __shared__ int smW[32];
    __shared__ int sOff;
    int tid = threadIdx.x, lane = tid & 31, wid = tid >> 5;
    if (tid == 0) sOff = 0;
    __syncthreads();
    for (int base = 0; base < NN; base += 1024) {
        int i = base + tid;
        int v = (i < NN) ? g_cnt[i] : 0;
        int inc = v;
#pragma unroll
        for (int o = 1; o < 32; o <<= 1) {
            int t = __shfl_up_sync(0xffffffffu, inc, o);
            if (lane >= o) inc += t;
        }
        if (lane == 31) smW[wid] = inc;
        __syncthreads();
        if (wid == 0) {
            int t = smW[lane];
#pragma unroll
            for (int o = 1; o < 32; o <<= 1) {
                int u = __shfl_up_sync(0xffffffffu, t, o);
                if (lane >= o) t += u;
            }
            smW[lane] = t;
        }
        __syncthreads();
        int warpOff = wid ? smW[wid - 1] : 0;
        if (i < NN) g_rowptr[i] = sOff + warpOff + inc - v;
        int blockTot = smW[31];
        __syncthreads();
        if (tid == 0) sOff += blockTot;
        __syncthreads();
    }
    if (tid == 0) g_rowptr[NN] = sOff;
}
__global__ void csr_fill_k(const int* __restrict__ src, const int* __restrict__ dst) {
    int e = blockIdx.x * blockDim.x + threadIdx.x;
    if (e >= EE) return;
    int d = dst[e];
    int pos = g_rowptr[d] + atomicAdd(&g_fill[d], 1);
    g_csrc[pos] = src[e];
}

// ================= tensor-core GEMM (3xTF32 split precision) =================
// C[n x 256] = A[n x din] @ B[din x 256]; din % 16 == 0.
// Block tile 128x64, BK=16, 256 threads (8 warps 4x2), warp tile 32x32.
// Each operand split hi/lo; acc += Ah*Bl + Al*Bh + Ah*Bh  (fp32 accumulate).
__global__ void __launch_bounds__(256) gemm_tc3(
        const float* __restrict__ A, const float* __restrict__ B,
        float* __restrict__ C, int n, int din) {
    __shared__ float Ah[128][20], Al[128][20];   // [m][k]; bank=(4m+k)%32 on frag loads
    __shared__ float Bh[16][72],  Bl[16][72];    // [k][n]; bank=(8k+n)%32 on frag loads
    const int tid  = threadIdx.x;
    const int wid  = tid >> 5;
    const int lane = tid & 31;
    const int row0 = blockIdx.y * 128;
    const int col0 = blockIdx.x * 64;
    const int wm0  = (wid >> 1) * 32;
    const int wn0  = (wid & 1) * 32;
    const int grp  = lane >> 2;              // 0..7
    const int qid  = lane & 3;               // 0..3

    float acc[2][4][4] = {};

    const int amr = tid >> 2;            // 0..63
    const int akc = (tid & 3) * 4;       // 0,4,8,12
    const int bkr = tid >> 4;            // 0..15
    const int bnc = (tid & 15) * 4;      // 0..60

    for (int kt = 0; kt < din; kt += 16) {
        // ---- A tile (128x16): hi/lo split, transposed store ----
#pragma unroll
        for (int p = 0; p < 2; p++) {
            int m  = amr + p * 64;
            int gr = row0 + m;
            float4 v = make_float4(0.f, 0.f, 0.f, 0.f);
            if (gr < n) v = *(const float4*)&A[(size_t)gr * din + kt + akc];
            uint32_t h0 = f2tf32(v.x), h1 = f2tf32(v.y), h2 = f2tf32(v.z), h3 = f2tf32(v.w);
            uint32_t* sh = (uint32_t*)&Ah[m][akc];
            sh[0] = h0; sh[1] = h1; sh[2] = h2; sh[3] = h3;
            uint32_t* sl = (uint32_t*)&Al[m][akc];
            sl[0] = f2tf32(v.x - __uint_as_float(h0));
            sl[1] = f2tf32(v.y - __uint_as_float(h1));
            sl[2] = f2tf32(v.z - __uint_as_float(h2));
            sl[3] = f2tf32(v.w - __uint_as_float(h3));
        }
        // ---- B tile (16x64): hi/lo split ----
        {
            float4 v = *(const float4*)&B[(size_t)(kt + bkr) * KH + col0 + bnc];
            uint32_t h0 = f2tf32(v.x), h1 = f2tf32(v.y), h2 = f2tf32(v.z), h3 = f2tf32(v.w);
            uint32_t* sh = (uint32_t*)&Bh[bkr][bnc];
            sh[0] = h0; sh[1] = h1; sh[2] = h2; sh[3] = h3;
            uint32_t* sl = (uint32_t*)&Bl[bkr][bnc];
            sl[0] = f2tf32(v.x - __uint_as_float(h0));
            sl[1] = f2tf32(v.y - __uint_as_float(h1));
            sl[2] = f2tf32(v.z - __uint_as_float(h2));
            sl[3] = f2tf32(v.w - __uint_as_float(h3));
        }
        __syncthreads();
#pragma unroll
        for (int k8 = 0; k8 < 16; k8 += 8) {
            uint32_t ah[2][4], al_[2][4], bh[4][2], bl[4][2];
#pragma unroll
            for (int mt = 0; mt < 2; mt++) {
                int r = wm0 + mt * 16 + grp;
                ah[mt][0]  = __float_as_uint(Ah[r][k8 + qid]);
                ah[mt][1]  = __float_as_uint(Ah[r + 8][k8 + qid]);
                ah[mt][2]  = __float_as_uint(Ah[r][k8 + qid + 4]);
                ah[mt][3]  = __float_as_uint(Ah[r + 8][k8 + qid + 4]);
                al_[mt][0] = __float_as_uint(Al[r][k8 + qid]);
                al_[mt][1] = __float_as_uint(Al[r + 8][k8 + qid]);
                al_[mt][2] = __float_as_uint(Al[r][k8 + qid + 4]);
                al_[mt][3] = __float_as_uint(Al[r + 8][k8 + qid + 4]);
            }
#pragma unroll
            for (int nt = 0; nt < 4; nt++) {
                int cN = wn0 + nt * 8 + grp;
                bh[nt][0] = __float_as_uint(Bh[k8 + qid][cN]);
                bh[nt][1] = __float_as_uint(Bh[k8 + qid + 4][cN]);
                bl[nt][0] = __float_as_uint(Bl[k8 + qid][cN]);
                bl[nt][1] = __float_as_uint(Bl[k8 + qid + 4][cN]);
            }
#define MMA_TF32(d, a, b)                                                      \
    asm volatile("mma.sync.aligned.m16n8k8.row.col.f32.tf32.tf32.f32 "         \
                 "{%0,%1,%2,%3}, {%4,%5,%6,%7}, {%8,%9}, {%0,%1,%2,%3};"       \
                 : "+f"(d[0]), "+f"(d[1]), "+f"(d[2]), "+f"(d[3])              \
                 : "r"(a[0]), "r"(a[1]), "r"(a[2]), "r"(a[3]),                 \
                   "r"(b[0]), "r"(b[1]))
#pragma unroll
            for (int mt = 0; mt < 2; mt++)
#pragma unroll
                for (int nt = 0; nt < 4; nt++) MMA_TF32(acc[mt][nt], ah[mt], bl[nt]);
#pragma unroll
            for (int mt = 0; mt < 2; mt++)
#pragma unroll
                for (int nt = 0; nt < 4; nt++) MMA_TF32(acc[mt][nt], al_[mt], bh[nt]);
#pragma unroll
            for (int mt = 0; mt < 2; mt++)
#pragma unroll
                for (int nt = 0; nt < 4; nt++) MMA_TF32(acc[mt][nt], ah[mt], bh[nt]);
#undef MMA_TF32
        }
        __syncthreads();
    }
    // ---- epilogue ----
#pragma unroll
    for (int mt = 0; mt < 2; mt++) {
#pragma unroll
        for (int nt = 0; nt < 4; nt++) {
            int r  = row0 + wm0 + mt * 16 + grp;
            int cC = col0 + wn0 + nt * 8 + qid * 2;
            if (r < n)
                *(float2*)&C[(size_t)r * KH + cC] = make_float2(acc[mt][nt][0], acc[mt][nt][1]);
            if (r + 8 < n)
                *(float2*)&C[(size_t)(r + 8) * KH + cC] = make_float2(acc[mt][nt][2], acc[mt][nt][3]);
        }
    }
}

// ================= attention projections el/er: warp per node =================
__global__ void attn_scores(const float* __restrict__ z, const float* __restrict__ al,
                            const float* __restrict__ arr) {
    int w    = (blockIdx.x * blockDim.x + threadIdx.x) >> 5;
    int lane = threadIdx.x & 31;
    if (w >= NN) return;
    const float* zr = z + (size_t)w * KH;
#pragma unroll
    for (int k = 0; k < 4; k++) {
        float z0 = zr[k * 64 + lane], z1 = zr[k * 64 + lane + 32];
        float vl = z0 * al[k * 64 + lane]  + z1 * al[k * 64 + lane + 32];
        float vr = z0 * arr[k * 64 + lane] + z1 * arr[k * 64 + lane + 32];
#pragma unroll
        for (int off = 16; off; off >>= 1) {
            vl += __shfl_down_sync(0xffffffffu, vl, off);
            vr += __shfl_down_sync(0xffffffffu, vr, off);
        }
        if (lane == 0) { g_el[w * 4 + k] = vl; g_er[w * 4 + k] = vr; }
    }
}

// ================= fused GAT attention + aggregation + combine =================
__global__ void gat_fused(const float* __restrict__ z, const float* __restrict__ res,
                          const float* __restrict__ bias, float* __restrict__ xout,
                          int mode) {
    __shared__ float sm[8][256];
    const int wIB  = threadIdx.x >> 5;
    const int n    = (blockIdx.x * blockDim.x + threadIdx.x) >> 5;
    const int lane = threadIdx.x & 31;
    if (n >= NN) return;
    const int r0 = g_rowptr[n];
    const int nE = g_rowptr[n + 1] - r0;
    const float4 erv = *(const float4*)&g_er[n * 4];
    const int myK = lane >> 3;

    float m0 = NEG_INF, m1 = NEG_INF, m2 = NEG_INF, m3 = NEG_INF;
    for (int b = 0; b < nE; b += 32) {
        int idx = b + lane;
        if (idx < nE) {
            int s = g_csrc[r0 + idx];
            float4 l = *(const float4*)&g_el[s * 4];
            m0 = fmaxf(m0, leaky02(l.x + erv.x));
            m1 = fmaxf(m1, leaky02(l.y + erv.y));
            m2 = fmaxf(m2, leaky02(l.z + erv.z));
            m3 = fmaxf(m3, leaky02(l.w + erv.w));
        }
    }
#pragma unroll
    for (int off = 16; off; off >>= 1) {
        m0 = fmaxf(m0, __shfl_xor_sync(0xffffffffu, m0, off));
        m1 = fmaxf(m1, __shfl_xor_sync(0xffffffffu, m1, off));
        m2 = fmaxf(m2, __shfl_xor_sync(0xffffffffu, m2, off));
        m3 = fmaxf(m3, __shfl_xor_sync(0xffffffffu, m3, off));
    }

    float acc[8] = {};
    float sl0 = 0.f, sl1 = 0.f, sl2 = 0.f, sl3 = 0.f;
    for (int b = 0; b < nE; b += 32) {
        int idx = b + lane;
        int cnt = min(32, nE - b);
        float p0 = 0.f, p1 = 0.f, p2 = 0.f, p3 = 0.f;
        int sN = 0;
        if (idx < nE) {
            sN = g_csrc[r0 + idx];
            float4 l = *(const float4*)&g_el[sN * 4];
            p0 = __expf(leaky02(l.x + erv.x) - m0);
            p1 = __expf(leaky02(l.y + erv.y) - m1);
            p2 = __expf(leaky02(l.z + erv.z) - m2);
            p3 = __expf(leaky02(l.w + erv.w) - m3);
            sl0 += p0; sl1 += p1; sl2 += p2; sl3 += p3;
        }
        for (int i = 0; i < cnt; i++) {
            int ss   = __shfl_sync(0xffffffffu, sN, i);
            float q0 = __shfl_sync(0xffffffffu, p0, i);
            float q1 = __shfl_sync(0xffffffffu, p1, i);
            float q2 = __shfl_sync(0xffffffffu, p2, i);
            float q3 = __shfl_sync(0xffffffffu, p3, i);
            float pa = (myK == 0) ? q0 : (myK == 1) ? q1 : (myK == 2) ? q2 : q3;
            const float4* zr = (const float4*)(z + (size_t)ss * KH + lane * 8);
            float4 za = zr[0], zb = zr[1];
            acc[0] += pa * za.x; acc[1] += pa * za.y;
            acc[2] += pa * za.z; acc[3] += pa * za.w;
            acc[4] += pa * zb.x; acc[5] += pa * zb.y;
            acc[6] += pa * zb.z; acc[7] += pa * zb.w;
        }
    }
#pragma unroll
    for (int off = 16; off; off >>= 1) {
        sl0 += __shfl_xor_sync(0xffffffffu, sl0, off);
        sl1 += __shfl_xor_sync(0xffffffffu, sl1, off);
        sl2 += __shfl_xor_sync(0xffffffffu, sl2, off);
        sl3 += __shfl_xor_sync(0xffffffffu, sl3, off);
    }
    float sk = (myK == 0) ? sl0 : (myK == 1) ? sl1 : (myK == 2) ? sl2 : sl3;
    float inv = (nE > 0) ? (1.0f / sk) : 0.0f;

    const int base = n * KH + lane * 8;
    float v[8];
    const float4* rp = (const float4*)(res + base);
    const float4* bp = (const float4*)(bias + lane * 8);
    float4 r4a = rp[0], r4b = rp[1], b4a = bp[0], b4b = bp[1];
    v[0] = acc[0] * inv + r4a.x + b4a.x; v[1] = acc[1] * inv + r4a.y + b4a.y;
    v[2] = acc[2] * inv + r4a.z + b4a.z; v[3] = acc[3] * inv + r4a.w + b4a.w;
    v[4] = acc[4] * inv + r4b.x + b4b.x; v[5] = acc[5] * inv + r4b.y + b4b.y;
    v[6] = acc[6] * inv + r4b.z + b4b.z; v[7] = acc[7] * inv + r4b.w + b4b.w;
#pragma unroll
    for (int j = 0; j < 8; j++) v[j] = v[j] > 0.f ? v[j] : 0.f;

    if (mode == 0) {
        float4* op = (float4*)(xout + base);
        op[0] = make_float4(v[0], v[1], v[2], v[3]);
        op[1] = make_float4(v[4], v[5], v[6], v[7]);
    } else {
#pragma unroll
        for (int j = 0; j < 8; j++) sm[wIB][lane * 8 + j] = v[j];
        __syncwarp();
        float h0 = (sm[wIB][lane]       + sm[wIB][64 + lane] +
                    sm[wIB][128 + lane] + sm[wIB][192 + lane]) * 0.25f;
        float h1 = (sm[wIB][32 + lane]  + sm[wIB][96 + lane] +
                    sm[wIB][160 + lane] + sm[wIB][224 + lane]) * 0.25f;
        g_x3[n * 64 + lane]      = h0;
        g_x3[n * 64 + lane + 32] = h1;
    }
}

// ================= readout + MLP =================
__global__ void init_readout() {
    int i = blockIdx.x * blockDim.x + threadIdx.x;
    if (i < GG * HH) { g_gs[i] = 0.0f; g_gm[i] = NEG_INF; }
}
__global__ void readout(const int* __restrict__ gid, const float* __restrict__ Wg,
                        const float* __restrict__ bg) {
    int w    = (blockIdx.x * blockDim.x + threadIdx.x) >> 5;
    int lane = threadIdx.x & 31;
    if (w >= NN) return;
    int g = gid[w];
    const float* xr = g_x3 + (size_t)w * 64;
    float x0 = xr[lane], x1 = xr[lane + 32];
    float p = x0 * Wg[lane] + x1 * Wg[lane + 32];
#pragma unroll
    for (int off = 16; off; off >>= 1) p += __shfl_down_sync(0xffffffffu, p, off);
    p = __shfl_sync(0xffffffffu, p, 0);
    float wgt = 1.0f / (1.0f + expf(-(p + bg[0])));
    atomicAdd(&g_gs[g * 64 + lane],      wgt * x0);
    atomicAdd(&g_gs[g * 64 + lane + 32], wgt * x1);
    atomicMaxF(&g_gm[g * 64 + lane],      x0);
    atomicMaxF(&g_gm[g * 64 + lane + 32], x1);
}
__global__ void mlp_head(const float* __restrict__ Wm1, const float* __restrict__ bm1,
                         const float* __restrict__ bn_g, const float* __restrict__ bn_b,
                         const float* __restrict__ bn_m, const float* __restrict__ bn_v,
                         const float* __restrict__ Wm2, const float* __restrict__ bm2,
                         float* __restrict__ out) {
    int g = blockIdx.x, j = threadIdx.x;   // 64 threads
    __shared__ float gf[128];
    gf[j]      = g_gs[g * 64 + j];
    gf[j + 64] = g_gm[g * 64 + j];
    __syncthreads();
    float acc = bm1[j];
#pragma unroll 8
    for (int i = 0; i < 128; i++) acc += gf[i] * Wm1[i * 64 + j];
    float y = acc > 0.0f ? acc : 0.0f;
    y = (y - bn_m[j]) * rsqrtf(bn_v[j] + 1e-5f) * bn_g[j] + bn_b[j];
    __shared__ float red[64];
    red[j] = y * Wm2[j];
    __syncthreads();
    if (j == 0) {
        float t = 0.0f;
#pragma unroll
        for (int i = 0; i < 64; i++) t += red[i];
        out[g] = 1.0f / (1.0f + expf(-(t + bm2[0])));
    }
}

// ================= host launcher =================
extern "C" void kernel_launch(void* const* d_in, const int* in_sizes, int n_in,
                              void* d_out, int out_size) {
    (void)in_sizes; (void)n_in; (void)out_size;
    const float* h     = (const float*)d_in[0];
    const int*   src   = (const int*)d_in[1];
    const int*   dst   = (const int*)d_in[2];
    const int*   gid   = (const int*)d_in[3];
    const float* W0    = (const float*)d_in[4];
    const float* al0   = (const float*)d_in[5];
    const float* ar0   = (const float*)d_in[6];
    const float* b0    = (const float*)d_in[7];
    const float* resW0 = (const float*)d_in[8];
    const float* W1    = (const float*)d_in[9];
    const float* al1   = (const float*)d_in[10];
    const float* ar1   = (const float*)d_in[11];
    const float* b1    = (const float*)d_in[12];
    const float* W2    = (const float*)d_in[13];
    const float* al2   = (const float*)d_in[14];
    const float* ar2   = (const float*)d_in[15];
    const float* b2    = (const float*)d_in[16];
    const float* Wg    = (const float*)d_in[17];
    const float* bg    = (const float*)d_in[18];
    const float* Wm1   = (const float*)d_in[19];
    const float* bm1   = (const float*)d_in[20];
    const float* bng   = (const float*)d_in[21];
    const float* bnb   = (const float*)d_in[22];
    const float* bnm   = (const float*)d_in[23];
    const float* bnv   = (const float*)d_in[24];
    const float* Wm2   = (const float*)d_in[25];
    const float* bm2   = (const float*)d_in[26];

    float *p_z, *p_res, *p_x;
    cudaGetSymbolAddress((void**)&p_z,   g_z);
    cudaGetSymbolAddress((void**)&p_res, g_res);
    cudaGetSymbolAddress((void**)&p_x,   g_x);

    dim3 gemmGrid(KH / 64, (NN + 127) / 128);
    const int edgeB  = (EE + 255) / 256;
    const int nWarpB = (NN + 7) / 8;      // warp per node, 8 warps/block

    // ---- CSR build (dst-grouped incoming edges) ----
    csr_zero<<<(NN + 255) / 256, 256>>>();
    csr_hist<<<edgeB, 256>>>(dst);
    csr_scan<<<1, 1024>>>();
    csr_fill_k<<<edgeB, 256>>>(src, dst);

    // ---- Layer 0 (flatten, learned residual) ----
    gemm_tc3<<<gemmGrid, 256>>>(h, W0, p_z, NN, FF);
    gemm_tc3<<<gemmGrid, 256>>>(h, resW0, p_res, NN, FF);
    attn_scores<<<nWarpB, 256>>>(p_z, al0, ar0);
    gat_fused<<<nWarpB, 256>>>(p_z, p_res, b0, p_x, 0);

    // ---- Layer 1 (flatten, identity residual) ----
    gemm_tc3<<<gemmGrid, 256>>>(p_x, W1, p_z, NN, KH);
    attn_scores<<<nWarpB, 256>>>(p_z, al1, ar1);
    gat_fused<<<nWarpB, 256>>>(p_z, p_x, b1, p_x, 0);

    // ---- Layer 2 (mean over heads, identity residual) ----
    gemm_tc3<<<gemmGrid, 256>>>(p_x, W2, p_z, NN, KH);
    attn_scores<<<nWarpB, 256>>>(p_z, al2, ar2);
    gat_fused<<<nWarpB, 256>>>(p_z, p_x, b2, nullptr, 1);

    // ---- Readout + MLP ----
    init_readout<<<(GG * HH + 255) / 256, 256>>>();
    readout<<<nWarpB, 256>>>(gid, Wg, bg);
    mlp_head<<<GG, 64>>>(Wm1, bm1, bng, bnb, bnm, bnv, Wm2, bm2, (float*)d_out);
}

// round 5
// speedup vs baseline: 1.9950x; 1.0181x over previous
#include <cuda_runtime.h>
#include <math.h>
#include <stdint.h>

#define NN 50000
#define EE 400000
#define GG 512
#define FF 128
#define KK 4
#define HH 64
#define KH 256   // K*H
#define NEG_INF __int_as_float(0xff800000)

// ---------------- device scratch (static, no runtime allocation) ----------------
__device__ float g_z[NN * KH];     // z = x @ W           [N, K, H]
__device__ float g_res[NN * KH];   // layer-0 residual GEMM output
__device__ float g_x[NN * KH];     // node features between layers
__device__ float g_el[NN * KK];
__device__ float g_er[NN * KK];
__device__ float g_x3[NN * HH];    // layer-2 output (head-mean) [N, 64]
__device__ float g_gs[GG * HH];    // weighted sum readout
__device__ float g_gm[GG * HH];    // max readout
// CSR (incoming edges grouped by dst)
__device__ int g_rowptr[NN + 1];
__device__ int g_cnt[NN];
__device__ int g_fill[NN];
__device__ int g_csrc[EE];

__device__ __forceinline__ void atomicMaxF(float* addr, float v) {
    if (v >= 0.0f) atomicMax((int*)addr, __float_as_int(v));
    else           atomicMin((unsigned int*)addr, __float_as_uint(v));
}
__device__ __forceinline__ float leaky02(float v) { return v > 0.0f ? v : 0.2f * v; }
__device__ __forceinline__ uint32_t f2tf32(float v) {
    uint32_t r;
    asm("cvt.rna.tf32.f32 %0, %1;" : "=r"(r) : "f"(v));
    return r;
}

// ================= CSR build =================
__global__ void csr_zero() {
    int i = blockIdx.x * blockDim.x + threadIdx.x;
    if (i < NN) { g_cnt[i] = 0; g_fill[i] = 0; }
}
__global__ void csr_hist(const int* __restrict__ dst) {
    int e = blockIdx.x * blockDim.x + threadIdx.x;
    if (e < EE) atomicAdd(&g_cnt[dst[e]], 1);
}
__global__ void csr_scan() {
    __shared__ int smW[32];
    __shared__ int sOff;
    int tid = threadIdx.x, lane = tid & 31, wid = tid >> 5;
    if (tid == 0) sOff = 0;
    __syncthreads();
    for (int base = 0; base < NN; base += 1024) {
        int i = base + tid;
        int v = (i < NN) ? g_cnt[i] : 0;
        int inc = v;
#pragma unroll
        for (int o = 1; o < 32; o <<= 1) {
            int t = __shfl_up_sync(0xffffffffu, inc, o);
            if (lane >= o) inc += t;
        }
        if (lane == 31) smW[wid] = inc;
        __syncthreads();
        if (wid == 0) {
            int t = smW[lane];
#pragma unroll
            for (int o = 1; o < 32; o <<= 1) {
                int u = __shfl_up_sync(0xffffffffu, t, o);
                if (lane >= o) t += u;
            }
            smW[lane] = t;
        }
        __syncthreads();
        int warpOff = wid ? smW[wid - 1] : 0;
        if (i < NN) g_rowptr[i] = sOff + warpOff + inc - v;
        int blockTot = smW[31];
        __syncthreads();
        if (tid == 0) sOff += blockTot;
        __syncthreads();
    }
    if (tid == 0) g_rowptr[NN] = sOff;
}
__global__ void csr_fill_k(const int* __restrict__ src, const int* __restrict__ dst) {
    int e = blockIdx.x * blockDim.x + threadIdx.x;
    if (e >= EE) return;
    int d = dst[e];
    int pos = g_rowptr[d] + atomicAdd(&g_fill[d], 1);
    g_csrc[pos] = src[e];
}

// ================= tensor-core GEMM (3xTF32) + fused attention epilogue =====
// C[n x 256] = A[n x din] @ B[din x 256]; din % 16 == 0.
// Block tile 128x64, BK=16, 256 threads (8 warps 4x2), warp tile 32x32.
// If alp != nullptr: blockIdx.x == head k; also emits
//   g_el[n,k] = sum_h C[n, k*64+h] * alp[k*64+h]   (and g_er with arp).
__global__ void __launch_bounds__(256) gemm_tc3(
        const float* __restrict__ A, const float* __restrict__ B,
        float* __restrict__ C, int n, int din,
        const float* __restrict__ alp, const float* __restrict__ arp) {
    __shared__ float Ah[128][20], Al[128][20];   // [m][k]
    __shared__ float Bh[16][72],  Bl[16][72];    // [k][n]
    __shared__ float sEl[2][128], sEr[2][128];
    const int tid  = threadIdx.x;
    const int wid  = tid >> 5;
    const int lane = tid & 31;
    const int row0 = blockIdx.y * 128;
    const int col0 = blockIdx.x * 64;
    const int wm0  = (wid >> 1) * 32;
    const int wn0  = (wid & 1) * 32;
    const int grp  = lane >> 2;              // 0..7
    const int qid  = lane & 3;               // 0..3

    float acc[2][4][4] = {};

    const int amr = tid >> 2;            // 0..63
    const int akc = (tid & 3) * 4;       // 0,4,8,12
    const int bkr = tid >> 4;            // 0..15
    const int bnc = (tid & 15) * 4;      // 0..60

    for (int kt = 0; kt < din; kt += 16) {
#pragma unroll
        for (int p = 0; p < 2; p++) {
            int m  = amr + p * 64;
            int gr = row0 + m;
            float4 v = make_float4(0.f, 0.f, 0.f, 0.f);
            if (gr < n) v = *(const float4*)&A[(size_t)gr * din + kt + akc];
            uint32_t h0 = f2tf32(v.x), h1 = f2tf32(v.y), h2 = f2tf32(v.z), h3 = f2tf32(v.w);
            uint32_t* sh = (uint32_t*)&Ah[m][akc];
            sh[0] = h0; sh[1] = h1; sh[2] = h2; sh[3] = h3;
            uint32_t* sl = (uint32_t*)&Al[m][akc];
            sl[0] = f2tf32(v.x - __uint_as_float(h0));
            sl[1] = f2tf32(v.y - __uint_as_float(h1));
            sl[2] = f2tf32(v.z - __uint_as_float(h2));
            sl[3] = f2tf32(v.w - __uint_as_float(h3));
        }
        {
            float4 v = *(const float4*)&B[(size_t)(kt + bkr) * KH + col0 + bnc];
            uint32_t h0 = f2tf32(v.x), h1 = f2tf32(v.y), h2 = f2tf32(v.z), h3 = f2tf32(v.w);
            uint32_t* sh = (uint32_t*)&Bh[bkr][bnc];
            sh[0] = h0; sh[1] = h1; sh[2] = h2; sh[3] = h3;
            uint32_t* sl = (uint32_t*)&Bl[bkr][bnc];
            sl[0] = f2tf32(v.x - __uint_as_float(h0));
            sl[1] = f2tf32(v.y - __uint_as_float(h1));
            sl[2] = f2tf32(v.z - __uint_as_float(h2));
            sl[3] = f2tf32(v.w - __uint_as_float(h3));
        }
        __syncthreads();
#pragma unroll
        for (int k8 = 0; k8 < 16; k8 += 8) {
            uint32_t ah[2][4], al_[2][4], bh[4][2], bl[4][2];
#pragma unroll
            for (int mt = 0; mt < 2; mt++) {
                int r = wm0 + mt * 16 + grp;
                ah[mt][0]  = __float_as_uint(Ah[r][k8 + qid]);
                ah[mt][1]  = __float_as_uint(Ah[r + 8][k8 + qid]);
                ah[mt][2]  = __float_as_uint(Ah[r][k8 + qid + 4]);
                ah[mt][3]  = __float_as_uint(Ah[r + 8][k8 + qid + 4]);
                al_[mt][0] = __float_as_uint(Al[r][k8 + qid]);
                al_[mt][1] = __float_as_uint(Al[r + 8][k8 + qid]);
                al_[mt][2] = __float_as_uint(Al[r][k8 + qid + 4]);
                al_[mt][3] = __float_as_uint(Al[r + 8][k8 + qid + 4]);
            }
#pragma unroll
            for (int nt = 0; nt < 4; nt++) {
                int cN = wn0 + nt * 8 + grp;
                bh[nt][0] = __float_as_uint(Bh[k8 + qid][cN]);
                bh[nt][1] = __float_as_uint(Bh[k8 + qid + 4][cN]);
                bl[nt][0] = __float_as_uint(Bl[k8 + qid][cN]);
                bl[nt][1] = __float_as_uint(Bl[k8 + qid + 4][cN]);
            }
#define MMA_TF32(d, a, b)                                                      \
    asm volatile("mma.sync.aligned.m16n8k8.row.col.f32.tf32.tf32.f32 "         \
                 "{%0,%1,%2,%3}, {%4,%5,%6,%7}, {%8,%9}, {%0,%1,%2,%3};"       \
                 : "+f"(d[0]), "+f"(d[1]), "+f"(d[2]), "+f"(d[3])              \
                 : "r"(a[0]), "r"(a[1]), "r"(a[2]), "r"(a[3]),                 \
                   "r"(b[0]), "r"(b[1]))
#pragma unroll
            for (int mt = 0; mt < 2; mt++)
#pragma unroll
                for (int nt = 0; nt < 4; nt++) MMA_TF32(acc[mt][nt], ah[mt], bl[nt]);
#pragma unroll
            for (int mt = 0; mt < 2; mt++)
#pragma unroll
                for (int nt = 0; nt < 4; nt++) MMA_TF32(acc[mt][nt], al_[mt], bh[nt]);
#pragma unroll
            for (int mt = 0; mt < 2; mt++)
#pragma unroll
                for (int nt = 0; nt < 4; nt++) MMA_TF32(acc[mt][nt], ah[mt], bh[nt]);
#undef MMA_TF32
        }
        __syncthreads();
    }
    // ---- epilogue: store C ----
#pragma unroll
    for (int mt = 0; mt < 2; mt++) {
#pragma unroll
        for (int nt = 0; nt < 4; nt++) {
            int r  = row0 + wm0 + mt * 16 + grp;
            int cC = col0 + wn0 + nt * 8 + qid * 2;
            if (r < n)
                *(float2*)&C[(size_t)r * KH + cC] = make_float2(acc[mt][nt][0], acc[mt][nt][1]);
            if (r + 8 < n)
                *(float2*)&C[(size_t)(r + 8) * KH + cC] = make_float2(acc[mt][nt][2], acc[mt][nt][3]);
        }
    }
    // ---- fused attention projections el/er for head k = blockIdx.x ----
    if (alp != nullptr) {
        const int hd = blockIdx.x;
        float alv[4][2], arv[4][2];
#pragma unroll
        for (int nt = 0; nt < 4; nt++)
#pragma unroll
            for (int j = 0; j < 2; j++) {
                int c = wn0 + nt * 8 + qid * 2 + j;
                alv[nt][j] = alp[hd * 64 + c];
                arv[nt][j] = arp[hd * 64 + c];
            }
#pragma unroll
        for (int mt = 0; mt < 2; mt++) {
            float ea = 0.f, eb = 0.f, ra = 0.f, rb = 0.f;
#pragma unroll
            for (int nt = 0; nt < 4; nt++) {
                ea += acc[mt][nt][0] * alv[nt][0] + acc[mt][nt][1] * alv[nt][1];
                eb += acc[mt][nt][2] * alv[nt][0] + acc[mt][nt][3] * alv[nt][1];
                ra += acc[mt][nt][0] * arv[nt][0] + acc[mt][nt][1] * arv[nt][1];
                rb += acc[mt][nt][2] * arv[nt][0] + acc[mt][nt][3] * arv[nt][1];
            }
#pragma unroll
            for (int o = 1; o < 4; o <<= 1) {
                ea += __shfl_down_sync(0xffffffffu, ea, o, 4);
                eb += __shfl_down_sync(0xffffffffu, eb, o, 4);
                ra += __shfl_down_sync(0xffffffffu, ra, o, 4);
                rb += __shfl_down_sync(0xffffffffu, rb, o, 4);
            }
            if (qid == 0) {
                int rr = wm0 + mt * 16 + grp;
                int hf = wn0 >> 5;
                sEl[hf][rr] = ea; sEl[hf][rr + 8] = eb;
                sEr[hf][rr] = ra; sEr[hf][rr + 8] = rb;
            }
        }
        __syncthreads();
        if (tid < 128) {
            int gr = row0 + tid;
            if (gr < n) {
                g_el[gr * 4 + hd] = sEl[0][tid] + sEl[1][tid];
                g_er[gr * 4 + hd] = sEr[0][tid] + sEr[1][tid];
            }
        }
    }
}

// ================= fused GAT attention + aggregation + combine =================
__global__ void gat_fused(const float* __restrict__ z, const float* __restrict__ res,
                          const float* __restrict__ bias, float* __restrict__ xout,
                          int mode) {
    __shared__ float sm[8][256];
    const int wIB  = threadIdx.x >> 5;
    const int n    = (blockIdx.x * blockDim.x + threadIdx.x) >> 5;
    const int lane = threadIdx.x & 31;
    if (n >= NN) return;
    const int r0 = g_rowptr[n];
    const int nE = g_rowptr[n + 1] - r0;
    const float4 erv = *(const float4*)&g_er[n * 4];
    const int myK = lane >> 3;

    // ---- pass 1: per-head max ----
    float m0 = NEG_INF, m1 = NEG_INF, m2 = NEG_INF, m3 = NEG_INF;
    for (int b = 0; b < nE; b += 32) {
        int idx = b + lane;
        if (idx < nE) {
            int s = g_csrc[r0 + idx];
            float4 l = *(const float4*)&g_el[s * 4];
            m0 = fmaxf(m0, leaky02(l.x + erv.x));
            m1 = fmaxf(m1, leaky02(l.y + erv.y));
            m2 = fmaxf(m2, leaky02(l.z + erv.z));
            m3 = fmaxf(m3, leaky02(l.w + erv.w));
        }
    }
#pragma unroll
    for (int off = 16; off; off >>= 1) {
        m0 = fmaxf(m0, __shfl_xor_sync(0xffffffffu, m0, off));
        m1 = fmaxf(m1, __shfl_xor_sync(0xffffffffu, m1, off));
        m2 = fmaxf(m2, __shfl_xor_sync(0xffffffffu, m2, off));
        m3 = fmaxf(m3, __shfl_xor_sync(0xffffffffu, m3, off));
    }

    // ---- pass 2: unnormalized weighted aggregation (4-wide ILP) ----
    float acc[8] = {};
    float sl0 = 0.f, sl1 = 0.f, sl2 = 0.f, sl3 = 0.f;
    for (int b = 0; b < nE; b += 32) {
        int idx = b + lane;
        int cnt = min(32, nE - b);
        float p0 = 0.f, p1 = 0.f, p2 = 0.f, p3 = 0.f;
        int sN = 0;
        if (idx < nE) {
            sN = g_csrc[r0 + idx];
            float4 l = *(const float4*)&g_el[sN * 4];
            p0 = __expf(leaky02(l.x + erv.x) - m0);
            p1 = __expf(leaky02(l.y + erv.y) - m1);
            p2 = __expf(leaky02(l.z + erv.z) - m2);
            p3 = __expf(leaky02(l.w + erv.w) - m3);
            sl0 += p0; sl1 += p1; sl2 += p2; sl3 += p3;
        }
        int i = 0;
        for (; i + 4 <= cnt; i += 4) {
            int ss[4]; float pa[4];
#pragma unroll
            for (int j = 0; j < 4; j++) {
                ss[j] = __shfl_sync(0xffffffffu, sN, i + j);
                float q0 = __shfl_sync(0xffffffffu, p0, i + j);
                float q1 = __shfl_sync(0xffffffffu, p1, i + j);
                float q2 = __shfl_sync(0xffffffffu, p2, i + j);
                float q3 = __shfl_sync(0xffffffffu, p3, i + j);
                pa[j] = (myK == 0) ? q0 : (myK == 1) ? q1 : (myK == 2) ? q2 : q3;
            }
            float4 za[4], zb[4];
#pragma unroll
            for (int j = 0; j < 4; j++) {
                const float4* zr = (const float4*)(z + (size_t)ss[j] * KH + lane * 8);
                za[j] = zr[0]; zb[j] = zr[1];
            }
#pragma unroll
            for (int j = 0; j < 4; j++) {
                acc[0] += pa[j] * za[j].x; acc[1] += pa[j] * za[j].y;
                acc[2] += pa[j] * za[j].z; acc[3] += pa[j] * za[j].w;
                acc[4] += pa[j] * zb[j].x; acc[5] += pa[j] * zb[j].y;
                acc[6] += pa[j] * zb[j].z; acc[7] += pa[j] * zb[j].w;
            }
        }
        for (; i < cnt; i++) {
            int ss   = __shfl_sync(0xffffffffu, sN, i);
            float q0 = __shfl_sync(0xffffffffu, p0, i);
            float q1 = __shfl_sync(0xffffffffu, p1, i);
            float q2 = __shfl_sync(0xffffffffu, p2, i);
            float q3 = __shfl_sync(0xffffffffu, p3, i);
            float pa = (myK == 0) ? q0 : (myK == 1) ? q1 : (myK == 2) ? q2 : q3;
            const float4* zr = (const float4*)(z + (size_t)ss * KH + lane * 8);
            float4 za = zr[0], zb = zr[1];
            acc[0] += pa * za.x; acc[1] += pa * za.y;
            acc[2] += pa * za.z; acc[3] += pa * za.w;
            acc[4] += pa * zb.x; acc[5] += pa * zb.y;
            acc[6] += pa * zb.z; acc[7] += pa * zb.w;
        }
    }
#pragma unroll
    for (int off = 16; off; off >>= 1) {
        sl0 += __shfl_xor_sync(0xffffffffu, sl0, off);
        sl1 += __shfl_xor_sync(0xffffffffu, sl1, off);
        sl2 += __shfl_xor_sync(0xffffffffu, sl2, off);
        sl3 += __shfl_xor_sync(0xffffffffu, sl3, off);
    }
    float sk = (myK == 0) ? sl0 : (myK == 1) ? sl1 : (myK == 2) ? sl2 : sl3;
    float inv = (nE > 0) ? (1.0f / sk) : 0.0f;

    const int base = n * KH + lane * 8;
    float v[8];
    const float4* rp = (const float4*)(res + base);
    const float4* bp = (const float4*)(bias + lane * 8);
    float4 r4a = rp[0], r4b = rp[1], b4a = bp[0], b4b = bp[1];
    v[0] = acc[0] * inv + r4a.x + b4a.x; v[1] = acc[1] * inv + r4a.y + b4a.y;
    v[2] = acc[2] * inv + r4a.z + b4a.z; v[3] = acc[3] * inv + r4a.w + b4a.w;
    v[4] = acc[4] * inv + r4b.x + b4b.x; v[5] = acc[5] * inv + r4b.y + b4b.y;
    v[6] = acc[6] * inv + r4b.z + b4b.z; v[7] = acc[7] * inv + r4b.w + b4b.w;
#pragma unroll
    for (int j = 0; j < 8; j++) v[j] = v[j] > 0.f ? v[j] : 0.f;

    if (mode == 0) {
        float4* op = (float4*)(xout + base);
        op[0] = make_float4(v[0], v[1], v[2], v[3]);
        op[1] = make_float4(v[4], v[5], v[6], v[7]);
    } else {
#pragma unroll
        for (int j = 0; j < 8; j++) sm[wIB][lane * 8 + j] = v[j];
        __syncwarp();
        float h0 = (sm[wIB][lane]       + sm[wIB][64 + lane] +
                    sm[wIB][128 + lane] + sm[wIB][192 + lane]) * 0.25f;
        float h1 = (sm[wIB][32 + lane]  + sm[wIB][96 + lane] +
                    sm[wIB][160 + lane] + sm[wIB][224 + lane]) * 0.25f;
        g_x3[n * 64 + lane]      = h0;
        g_x3[n * 64 + lane + 32] = h1;
    }
}

// ================= readout + MLP =================
__global__ void init_readout() {
    int i = blockIdx.x * blockDim.x + threadIdx.x;
    if (i < GG * HH) { g_gs[i] = 0.0f; g_gm[i] = NEG_INF; }
}
__global__ void readout(const int* __restrict__ gid, const float* __restrict__ Wg,
                        const float* __restrict__ bg) {
    int w    = (blockIdx.x * blockDim.x + threadIdx.x) >> 5;
    int lane = threadIdx.x & 31;
    if (w >= NN) return;
    int g = gid[w];
    const float* xr = g_x3 + (size_t)w * 64;
    float x0 = xr[lane], x1 = xr[lane + 32];
    float p = x0 * Wg[lane] + x1 * Wg[lane + 32];
#pragma unroll
    for (int off = 16; off; off >>= 1) p += __shfl_down_sync(0xffffffffu, p, off);
    p = __shfl_sync(0xffffffffu, p, 0);
    float wgt = 1.0f / (1.0f + expf(-(p + bg[0])));
    atomicAdd(&g_gs[g * 64 + lane],      wgt * x0);
    atomicAdd(&g_gs[g * 64 + lane + 32], wgt * x1);
    atomicMaxF(&g_gm[g * 64 + lane],      x0);
    atomicMaxF(&g_gm[g * 64 + lane + 32], x1);
}
__global__ void mlp_head(const float* __restrict__ Wm1, const float* __restrict__ bm1,
                         const float* __restrict__ bn_g, const float* __restrict__ bn_b,
                         const float* __restrict__ bn_m, const float* __restrict__ bn_v,
                         const float* __restrict__ Wm2, const float* __restrict__ bm2,
                         float* __restrict__ out) {
    int g = blockIdx.x, j = threadIdx.x;   // 64 threads
    __shared__ float gf[128];
    gf[j]      = g_gs[g * 64 + j];
    gf[j + 64] = g_gm[g * 64 + j];
    __syncthreads();
    float acc = bm1[j];
#pragma unroll 8
    for (int i = 0; i < 128; i++) acc += gf[i] * Wm1[i * 64 + j];
    float y = acc > 0.0f ? acc : 0.0f;
    y = (y - bn_m[j]) * rsqrtf(bn_v[j] + 1e-5f) * bn_g[j] + bn_b[j];
    __shared__ float red[64];
    red[j] = y * Wm2[j];
    __syncthreads();
    if (j == 0) {
        float t = 0.0f;
#pragma unroll
        for (int i = 0; i < 64; i++) t += red[i];
        out[g] = 1.0f / (1.0f + expf(-(t + bm2[0])));
    }
}

// ================= host launcher =================
extern "C" void kernel_launch(void* const* d_in, const int* in_sizes, int n_in,
                              void* d_out, int out_size) {
    (void)in_sizes; (void)n_in; (void)out_size;
    const float* h     = (const float*)d_in[0];
    const int*   src   = (const int*)d_in[1];
    const int*   dst   = (const int*)d_in[2];
    const int*   gid   = (const int*)d_in[3];
    const float* W0    = (const float*)d_in[4];
    const float* al0   = (const float*)d_in[5];
    const float* ar0   = (const float*)d_in[6];
    const float* b0    = (const float*)d_in[7];
    const float* resW0 = (const float*)d_in[8];
    const float* W1    = (const float*)d_in[9];
    const float* al1   = (const float*)d_in[10];
    const float* ar1   = (const float*)d_in[11];
    const float* b1    = (const float*)d_in[12];
    const float* W2    = (const float*)d_in[13];
    const float* al2   = (const float*)d_in[14];
    const float* ar2   = (const float*)d_in[15];
    const float* b2    = (const float*)d_in[16];
    const float* Wg    = (const float*)d_in[17];
    const float* bg    = (const float*)d_in[18];
    const float* Wm1   = (const float*)d_in[19];
    const float* bm1   = (const float*)d_in[20];
    const float* bng   = (const float*)d_in[21];
    const float* bnb   = (const float*)d_in[22];
    const float* bnm   = (const float*)d_in[23];
    const float* bnv   = (const float*)d_in[24];
    const float* Wm2   = (const float*)d_in[25];
    const float* bm2   = (const float*)d_in[26];

    float *p_z, *p_res, *p_x;
    cudaGetSymbolAddress((void**)&p_z,   g_z);
    cudaGetSymbolAddress((void**)&p_res, g_res);
    cudaGetSymbolAddress((void**)&p_x,   g_x);

    dim3 gemmGrid(KH / 64, (NN + 127) / 128);
    const int edgeB  = (EE + 255) / 256;
    const int nWarpB = (NN + 7) / 8;      // warp per node, 8 warps/block

    // ---- CSR build (dst-grouped incoming edges) ----
    csr_zero<<<(NN + 255) / 256, 256>>>();
    csr_hist<<<edgeB, 256>>>(dst);
    csr_scan<<<1, 1024>>>();
    csr_fill_k<<<edgeB, 256>>>(src, dst);

    // ---- Layer 0 (flatten, learned residual) ----
    gemm_tc3<<<gemmGrid, 256>>>(h, W0, p_z, NN, FF, al0, ar0);
    gemm_tc3<<<gemmGrid, 256>>>(h, resW0, p_res, NN, FF, nullptr, nullptr);
    gat_fused<<<nWarpB, 256>>>(p_z, p_res, b0, p_x, 0);

    // ---- Layer 1 (flatten, identity residual) ----
    gemm_tc3<<<gemmGrid, 256>>>(p_x, W1, p_z, NN, KH, al1, ar1);
    gat_fused<<<nWarpB, 256>>>(p_z, p_x, b1, p_x, 0);

    // ---- Layer 2 (mean over heads, identity residual) ----
    gemm_tc3<<<gemmGrid, 256>>>(p_x, W2, p_z, NN, KH, al2, ar2);
    gat_fused<<<nWarpB, 256>>>(p_z, p_x, b2, nullptr, 1);

    // ---- Readout + MLP ----
    init_readout<<<(GG * HH + 255) / 256, 256>>>();
    readout<<<nWarpB, 256>>>(gid, Wg, bg);
    mlp_head<<<GG, 64>>>(Wm1, bm1, bng, bnb, bnm, bnv, Wm2, bm2, (float*)d_out);
}